// round 1
// baseline (speedup 1.0000x reference)
#include <cuda_runtime.h>
#include <math.h>

#define Bn  2
#define Tn  1024
#define Hn  16
#define HDn 128
#define Dn  2048
#define XLn 1024
#define KVn 2048

// ---------------- scratch (static device allocations; no cudaMalloc) ----------
__device__ float g_q[Bn*Hn*Tn*HDn];            // (B,H,T,hd)       16 MB
__device__ float g_k[Bn*Hn*KVn*HDn];           // (B,H,KV,hd)      32 MB
__device__ float g_v[Bn*Hn*KVn*HDn];           // (B,H,KV,hd)      32 MB
__device__ float g_s[(size_t)Bn*Hn*Tn*KVn];    // (B*H,T,KV)      256 MB
__device__ float g_y[Bn*Tn*Dn];                // (B,T,C)          16 MB

// ---------------- shared GEMM cores -------------------------------------------
// NT: C[M,N] = A(MxK, row-major lda) * B(NxK, row-major ldb)^T
// 64x64 block tile, 256 threads, 4x4 micro tile, K-step 16.
__device__ __forceinline__ void gemm_nt_core(
    const float* __restrict__ A, int lda,
    const float* __restrict__ Bm, int ldb,
    int K, int bm, int bn,
    float (&acc)[4][4],
    float (*As)[64], float (*Bs)[64])
{
    const int tid = threadIdx.x;
    const int tm = tid & 15, tn = tid >> 4;
    const int lr = tid >> 2, lc = (tid & 3) << 2;
    for (int kt = 0; kt < K; kt += 16) {
        float4 a4 = *(const float4*)(A  + (size_t)(bm + lr) * lda + kt + lc);
        float4 b4 = *(const float4*)(Bm + (size_t)(bn + lr) * ldb + kt + lc);
        As[lc+0][lr]=a4.x; As[lc+1][lr]=a4.y; As[lc+2][lr]=a4.z; As[lc+3][lr]=a4.w;
        Bs[lc+0][lr]=b4.x; Bs[lc+1][lr]=b4.y; Bs[lc+2][lr]=b4.z; Bs[lc+3][lr]=b4.w;
        __syncthreads();
#pragma unroll
        for (int kk = 0; kk < 16; kk++) {
            float4 av = *(const float4*)&As[kk][tm<<2];
            float4 bv = *(const float4*)&Bs[kk][tn<<2];
            float ar[4]={av.x,av.y,av.z,av.w};
            float br[4]={bv.x,bv.y,bv.z,bv.w};
#pragma unroll
            for (int i=0;i<4;i++)
#pragma unroll
                for (int j=0;j<4;j++)
                    acc[i][j] = fmaf(ar[i], br[j], acc[i][j]);
        }
        __syncthreads();
    }
}

// NN: C[M,N] = A(MxK, row-major lda) * B(KxN, row-major ldb)
__device__ __forceinline__ void gemm_nn_core(
    const float* __restrict__ A, int lda,
    const float* __restrict__ Bm, int ldb,
    int K, int bm, int bn,
    float (&acc)[4][4],
    float (*As)[64], float (*Bs)[64])
{
    const int tid = threadIdx.x;
    const int tm = tid & 15, tn = tid >> 4;
    const int lr = tid >> 2, lc = (tid & 3) << 2;
    const int br = tid >> 4, bc = (tid & 15) << 2;
    for (int kt = 0; kt < K; kt += 16) {
        float4 a4 = *(const float4*)(A  + (size_t)(bm + lr) * lda + kt + lc);
        float4 b4 = *(const float4*)(Bm + (size_t)(kt + br) * ldb + bn + bc);
        As[lc+0][lr]=a4.x; As[lc+1][lr]=a4.y; As[lc+2][lr]=a4.z; As[lc+3][lr]=a4.w;
        *(float4*)&Bs[br][bc] = b4;
        __syncthreads();
#pragma unroll
        for (int kk = 0; kk < 16; kk++) {
            float4 av = *(const float4*)&As[kk][tm<<2];
            float4 bv = *(const float4*)&Bs[kk][tn<<2];
            float ar[4]={av.x,av.y,av.z,av.w};
            float br2[4]={bv.x,bv.y,bv.z,bv.w};
#pragma unroll
            for (int i=0;i<4;i++)
#pragma unroll
                for (int j=0;j<4;j++)
                    acc[i][j] = fmaf(ar[i], br2[j], acc[i][j]);
        }
        __syncthreads();
    }
}

// ---------------- kernel 1: qkv = x @ w_qkv^T, scatter into q/k/v --------------
__global__ __launch_bounds__(256) void k_qkv_gemm(
    const float* __restrict__ x, const float* __restrict__ w_qkv)
{
    __shared__ __align__(16) float As[16][64];
    __shared__ __align__(16) float Bs[16][64];
    const int bm = blockIdx.y * 64, bn = blockIdx.x * 64;
    float acc[4][4] = {};
    gemm_nt_core(x, Dn, w_qkv, Dn, Dn, bm, bn, acc, As, Bs);
    const int tm = threadIdx.x & 15, tn = threadIdx.x >> 4;
#pragma unroll
    for (int i=0;i<4;i++) {
        const int m = bm + (tm<<2) + i;
        const int b = m >> 10, t = m & 1023;
#pragma unroll
        for (int j=0;j<4;j++) {
            const int n = bn + (tn<<2) + j;
            const int sec = n >> 11, c = n & 2047;
            const int h = c >> 7, d = c & 127;
            float v = acc[i][j];
            if (sec == 0)      g_q[((size_t)(b*Hn+h)*Tn  + t      )*HDn + d] = v;
            else if (sec == 1) g_k[((size_t)(b*Hn+h)*KVn + XLn + t)*HDn + d] = v;
            else               g_v[((size_t)(b*Hn+h)*KVn + XLn + t)*HDn + d] = v;
        }
    }
}

// ---------------- kernel 2: k_xl + pos_emb, v_xl → head layout -----------------
__global__ __launch_bounds__(256) void k_xl_prep(
    const float* __restrict__ k_xl, const float* __restrict__ v_xl,
    const float* __restrict__ pos_emb)
{
    const int idx = blockIdx.x * 256 + threadIdx.x;
    if (idx >= Bn*XLn*Dn) return;
    const int c = idx & 2047;
    const int pos = (idx >> 11) & 1023;
    const int b = idx >> 21;
    const int h = c >> 7, d = c & 127;
    const size_t dst = ((size_t)(b*Hn+h)*KVn + pos)*HDn + d;
    g_k[dst] = k_xl[idx] + pos_emb[pos*Dn + c];
    g_v[dst] = v_xl[idx];
}

// ---------------- kernel 3: RoPE on q and new k --------------------------------
__global__ __launch_bounds__(256) void k_rope(
    const float* __restrict__ cosb, const float* __restrict__ sinb)
{
    const int idx = blockIdx.x * 256 + threadIdx.x;
    const int half = Bn*Hn*Tn*(HDn/2);   // 2^21
    if (idx >= 2*half) return;
    const int isK = idx >= half;
    const int p = idx - (isK ? half : 0);
    const int j = p & 63;
    const int t = (p >> 6) & 1023;
    const int h = (p >> 16) & 15;
    const int b = p >> 20;
    float* buf = isK ? g_k : g_q;
    const size_t base = isK
        ? ((size_t)(b*Hn+h)*KVn + XLn + t)*HDn + 2*j
        : ((size_t)(b*Hn+h)*Tn  + t      )*HDn + 2*j;
    const float c = cosb[t*64 + j];
    const float s = sinb[t*64 + j];
    const float x1 = buf[base], x2 = buf[base+1];
    buf[base]   = x1*c - x2*s;
    buf[base+1] = x1*s + x2*c;
}

// ---------------- kernel 4: scores = Q K^T * scale (+ causal mask) -------------
__global__ __launch_bounds__(256) void k_scores(const int* __restrict__ causal)
{
    __shared__ __align__(16) float As[16][64];
    __shared__ __align__(16) float Bs[16][64];
    __shared__ int cflag;
    if (threadIdx.x == 0) cflag = *causal;
    const int z = blockIdx.z;                 // b*H + h
    const int bm = blockIdx.y * 64, bn = blockIdx.x * 64;
    const float* A  = g_q + (size_t)z*Tn*HDn;
    const float* Bm = g_k + (size_t)z*KVn*HDn;
    float acc[4][4] = {};
    gemm_nt_core(A, HDn, Bm, HDn, HDn, bm, bn, acc, As, Bs);
    const int tm = threadIdx.x & 15, tn = threadIdx.x >> 4;
    const float scale = 0.08838834764831845f;  // 1/sqrt(128)
    float* C = g_s + (size_t)z*Tn*KVn;
    const int cz = cflag;
#pragma unroll
    for (int i=0;i<4;i++) {
        const int m = bm + (tm<<2) + i;
#pragma unroll
        for (int j=0;j<4;j++) {
            const int n = bn + (tn<<2) + j;
            float v = acc[i][j] * scale;
            if (cz && n > m + (KVn - Tn)) v = -3.402823466e38f;
            C[(size_t)m*KVn + n] = v;
        }
    }
}

// ---------------- kernel 5: row softmax over 2048 ------------------------------
__global__ __launch_bounds__(256) void k_softmax()
{
    const size_t row = blockIdx.x;
    float* p = g_s + row * (size_t)KVn;
    const int tid = threadIdx.x;
    float4 a = *(float4*)(p + tid*4);
    float4 b = *(float4*)(p + 1024 + tid*4);
    __shared__ float red[8];

    float m = fmaxf(fmaxf(fmaxf(a.x,a.y),fmaxf(a.z,a.w)),
                    fmaxf(fmaxf(b.x,b.y),fmaxf(b.z,b.w)));
#pragma unroll
    for (int o=16;o>0;o>>=1) m = fmaxf(m, __shfl_xor_sync(0xffffffffu, m, o));
    if ((tid & 31) == 0) red[tid>>5] = m;
    __syncthreads();
    float M = red[0];
#pragma unroll
    for (int w=1;w<8;w++) M = fmaxf(M, red[w]);
    __syncthreads();

    a.x = __expf(a.x - M); a.y = __expf(a.y - M);
    a.z = __expf(a.z - M); a.w = __expf(a.w - M);
    b.x = __expf(b.x - M); b.y = __expf(b.y - M);
    b.z = __expf(b.z - M); b.w = __expf(b.w - M);
    float s = a.x+a.y+a.z+a.w+b.x+b.y+b.z+b.w;
#pragma unroll
    for (int o=16;o>0;o>>=1) s += __shfl_xor_sync(0xffffffffu, s, o);
    if ((tid & 31) == 0) red[tid>>5] = s;
    __syncthreads();
    float S = 0.f;
#pragma unroll
    for (int w=0;w<8;w++) S += red[w];
    const float inv = 1.0f / S;

    a.x*=inv; a.y*=inv; a.z*=inv; a.w*=inv;
    b.x*=inv; b.y*=inv; b.z*=inv; b.w*=inv;
    *(float4*)(p + tid*4) = a;
    *(float4*)(p + 1024 + tid*4) = b;
}

// ---------------- kernel 6: y = P V  (NN), store to (B,T,C) --------------------
__global__ __launch_bounds__(256) void k_pv()
{
    __shared__ __align__(16) float As[16][64];
    __shared__ __align__(16) float Bs[16][64];
    const int z = blockIdx.z;
    const int b = z >> 4, h = z & 15;
    const int bm = blockIdx.y * 64, bn = blockIdx.x * 64;
    const float* A  = g_s + (size_t)z*Tn*KVn;
    const float* Bm = g_v + (size_t)z*KVn*HDn;
    float acc[4][4] = {};
    gemm_nn_core(A, KVn, Bm, HDn, KVn, bm, bn, acc, As, Bs);
    const int tm = threadIdx.x & 15, tn = threadIdx.x >> 4;
#pragma unroll
    for (int i=0;i<4;i++) {
        const int m = bm + (tm<<2) + i;     // query t
#pragma unroll
        for (int j=0;j<4;j++) {
            const int n = bn + (tn<<2) + j; // head dim d
            g_y[((size_t)(b*Tn + m))*Dn + h*HDn + n] = acc[i][j];
        }
    }
}

// ---------------- kernel 7: out = y @ w_proj^T ---------------------------------
__global__ __launch_bounds__(256) void k_proj(
    const float* __restrict__ w_proj, float* __restrict__ out)
{
    __shared__ __align__(16) float As[16][64];
    __shared__ __align__(16) float Bs[16][64];
    const int bm = blockIdx.y * 64, bn = blockIdx.x * 64;
    float acc[4][4] = {};
    gemm_nt_core(g_y, Dn, w_proj, Dn, Dn, bm, bn, acc, As, Bs);
    const int tm = threadIdx.x & 15, tn = threadIdx.x >> 4;
#pragma unroll
    for (int i=0;i<4;i++) {
        const int m = bm + (tm<<2) + i;
#pragma unroll
        for (int j=0;j<4;j++) {
            const int n = bn + (tn<<2) + j;
            out[(size_t)m*Dn + n] = acc[i][j];
        }
    }
}

// ---------------- launch ------------------------------------------------------
extern "C" void kernel_launch(void* const* d_in, const int* in_sizes, int n_in,
                              void* d_out, int out_size)
{
    const float* x       = (const float*)d_in[0];
    const float* cosb    = (const float*)d_in[1];
    const float* sinb    = (const float*)d_in[2];
    const float* k_xl    = (const float*)d_in[3];
    const float* v_xl    = (const float*)d_in[4];
    const float* pos_emb = (const float*)d_in[5];
    const float* w_qkv   = (const float*)d_in[6];
    const float* w_proj  = (const float*)d_in[7];
    const int*   causal  = (const int*)d_in[8];
    float* out = (float*)d_out;

    // 1) qkv GEMM: (2048 x 2048) x (6144 x 2048)^T
    k_qkv_gemm<<<dim3(3*Dn/64, Bn*Tn/64), 256>>>(x, w_qkv);

    // 2) XL cache prep
    k_xl_prep<<<(Bn*XLn*Dn)/256, 256>>>(k_xl, v_xl, pos_emb);

    // 3) RoPE on q and new-k
    k_rope<<<(2*Bn*Hn*Tn*(HDn/2))/256, 256>>>(cosb, sinb);

    // 4) scores (batched over 32 heads)
    k_scores<<<dim3(KVn/64, Tn/64, Bn*Hn), 256>>>(causal);

    // 5) softmax per row
    k_softmax<<<Bn*Hn*Tn, 256>>>();

    // 6) P @ V
    k_pv<<<dim3(HDn/64, Tn/64, Bn*Hn), 256>>>();

    // 7) output projection
    k_proj<<<dim3(Dn/64, Bn*Tn/64), 256>>>(w_proj, out);
}

// round 3
// speedup vs baseline: 1.6360x; 1.6360x over previous
#include <cuda_runtime.h>
#include <math.h>

#define Bn  2
#define Tn  1024
#define Hn  16
#define HDn 128
#define Dn  2048
#define XLn 1024
#define KVn 2048

// ---------------- scratch -----------------------------------------------------
__device__ float g_q[Bn*Hn*Tn*HDn];            // (B,H,T,hd)       16 MB
__device__ float g_k[Bn*Hn*KVn*HDn];           // (B,H,KV,hd)      32 MB
__device__ float g_v[Bn*Hn*KVn*HDn];           // (B,H,KV,hd)      32 MB
__device__ float g_s[(size_t)Bn*Hn*Tn*KVn];    // (B*H,T,KV)      256 MB
__device__ float g_y[Bn*Tn*Dn];                // (B,T,C)          16 MB

// ---------------- tf32 helpers ------------------------------------------------
__device__ __forceinline__ float f2tf(float x) {
    unsigned r; asm("cvt.rna.tf32.f32 %0, %1;" : "=r"(r) : "f"(x));
    return __uint_as_float(r);
}

__device__ __forceinline__ void mma8(float* d,
    unsigned a0, unsigned a1, unsigned a2, unsigned a3,
    unsigned b0, unsigned b1)
{
    asm volatile(
        "mma.sync.aligned.m16n8k8.row.col.f32.tf32.tf32.f32 "
        "{%0,%1,%2,%3}, {%4,%5,%6,%7}, {%8,%9}, {%0,%1,%2,%3};"
        : "+f"(d[0]), "+f"(d[1]), "+f"(d[2]), "+f"(d[3])
        : "r"(a0), "r"(a1), "r"(a2), "r"(a3), "r"(b0), "r"(b1));
}

// Load a 64(rows) x 32(k) tile from row-major src (ld), converting to tf32.
// src must already point at the tile's first row.
__device__ __forceinline__ void load_tile_rowk(
    float (*S)[33], const float* __restrict__ src, size_t ld, int kt)
{
    const int tid = threadIdx.x;
#pragma unroll
    for (int p = 0; p < 4; p++) {
        const int idx = p*512 + tid*4;
        const int r = idx >> 5, c = idx & 31;
        float4 v = *(const float4*)(src + (size_t)r*ld + kt + c);
        S[r][c+0] = f2tf(v.x);
        S[r][c+1] = f2tf(v.y);
        S[r][c+2] = f2tf(v.z);
        S[r][c+3] = f2tf(v.w);
    }
}

// Load a 32(k) x 64(n) tile from row-major (K x N) src into S[n][k] (NN path).
__device__ __forceinline__ void load_tile_kn(
    float (*S)[33], const float* __restrict__ src, size_t ld, int kt)
{
    const int tid = threadIdx.x;
#pragma unroll
    for (int p = 0; p < 4; p++) {
        const int idx = p*512 + tid*4;
        const int kr = idx >> 6, nc = idx & 63;
        float4 v = *(const float4*)(src + (size_t)(kt+kr)*ld + nc);
        S[nc+0][kr] = f2tf(v.x);
        S[nc+1][kr] = f2tf(v.y);
        S[nc+2][kr] = f2tf(v.z);
        S[nc+3][kr] = f2tf(v.w);
    }
}

// One 32-wide K step of warp-level mma: acc[2][4][4] covers 32x32 per warp.
__device__ __forceinline__ void compute_kt(
    float (&acc)[2][4][4], const float (*As)[33], const float (*Bs)[33],
    int wm, int wn, int lane)
{
    const int gid = lane >> 2, tig = lane & 3;
#pragma unroll
    for (int k8 = 0; k8 < 4; k8++) {
        const int k0 = k8*8;
        unsigned a[2][4], b[4][2];
#pragma unroll
        for (int mi = 0; mi < 2; mi++) {
            const int r = wm + mi*16 + gid;
            a[mi][0] = __float_as_uint(As[r  ][k0+tig  ]);
            a[mi][1] = __float_as_uint(As[r+8][k0+tig  ]);
            a[mi][2] = __float_as_uint(As[r  ][k0+tig+4]);
            a[mi][3] = __float_as_uint(As[r+8][k0+tig+4]);
        }
#pragma unroll
        for (int ni = 0; ni < 4; ni++) {
            const int rn = wn + ni*8 + gid;
            b[ni][0] = __float_as_uint(Bs[rn][k0+tig  ]);
            b[ni][1] = __float_as_uint(Bs[rn][k0+tig+4]);
        }
#pragma unroll
        for (int mi = 0; mi < 2; mi++)
#pragma unroll
            for (int ni = 0; ni < 4; ni++)
                mma8(acc[mi][ni], a[mi][0], a[mi][1], a[mi][2], a[mi][3],
                     b[ni][0], b[ni][1]);
    }
}

// ---------------- kernel 1: qkv = x @ w_qkv^T, scatter into q/k/v --------------
__global__ __launch_bounds__(128) void k_qkv_gemm(
    const float* __restrict__ x, const float* __restrict__ w_qkv)
{
    __shared__ __align__(16) float As[64][33];
    __shared__ __align__(16) float Bs[64][33];
    const int bm = blockIdx.y * 64, bn = blockIdx.x * 64;
    const int warp = threadIdx.x >> 5, lane = threadIdx.x & 31;
    const int wm = (warp & 1) * 32, wn = (warp >> 1) * 32;
    float acc[2][4][4] = {};
    for (int kt = 0; kt < Dn; kt += 32) {
        load_tile_rowk(As, x     + (size_t)bm*Dn, Dn, kt);
        load_tile_rowk(Bs, w_qkv + (size_t)bn*Dn, Dn, kt);
        __syncthreads();
        compute_kt(acc, As, Bs, wm, wn, lane);
        __syncthreads();
    }
    const int gid = lane >> 2, tig = lane & 3;
#pragma unroll
    for (int mi = 0; mi < 2; mi++) {
#pragma unroll
        for (int rr = 0; rr < 2; rr++) {
            const int m = bm + wm + mi*16 + gid + rr*8;
            const int b = m >> 10, t = m & 1023;
#pragma unroll
            for (int ni = 0; ni < 4; ni++) {
                const int n = bn + wn + ni*8 + tig*2;
                const int sec = n >> 11, c = n & 2047;
                const int h = c >> 7, d = c & 127;
                float2 v = make_float2(acc[mi][ni][rr*2], acc[mi][ni][rr*2+1]);
                if (sec == 0)
                    *(float2*)&g_q[((size_t)(b*Hn+h)*Tn  + t      )*HDn + d] = v;
                else if (sec == 1)
                    *(float2*)&g_k[((size_t)(b*Hn+h)*KVn + XLn + t)*HDn + d] = v;
                else
                    *(float2*)&g_v[((size_t)(b*Hn+h)*KVn + XLn + t)*HDn + d] = v;
            }
        }
    }
}

// ---------------- kernel 2: k_xl + pos_emb, v_xl → head layout -----------------
__global__ __launch_bounds__(256) void k_xl_prep(
    const float* __restrict__ k_xl, const float* __restrict__ v_xl,
    const float* __restrict__ pos_emb)
{
    const int idx = blockIdx.x * 256 + threadIdx.x;
    if (idx >= Bn*XLn*Dn) return;
    const int c = idx & 2047;
    const int pos = (idx >> 11) & 1023;
    const int b = idx >> 21;
    const int h = c >> 7, d = c & 127;
    const size_t dst = ((size_t)(b*Hn+h)*KVn + pos)*HDn + d;
    g_k[dst] = k_xl[idx] + pos_emb[pos*Dn + c];
    g_v[dst] = v_xl[idx];
}

// ---------------- kernel 3: RoPE on q and new k --------------------------------
__global__ __launch_bounds__(256) void k_rope(
    const float* __restrict__ cosb, const float* __restrict__ sinb)
{
    const int idx = blockIdx.x * 256 + threadIdx.x;
    const int half = Bn*Hn*Tn*(HDn/2);
    if (idx >= 2*half) return;
    const int isK = idx >= half;
    const int p = idx - (isK ? half : 0);
    const int j = p & 63;
    const int t = (p >> 6) & 1023;
    const int h = (p >> 16) & 15;
    const int b = p >> 20;
    float* buf = isK ? g_k : g_q;
    const size_t base = isK
        ? ((size_t)(b*Hn+h)*KVn + XLn + t)*HDn + 2*j
        : ((size_t)(b*Hn+h)*Tn  + t      )*HDn + 2*j;
    const float c = cosb[t*64 + j];
    const float s = sinb[t*64 + j];
    const float x1 = buf[base], x2 = buf[base+1];
    buf[base]   = x1*c - x2*s;
    buf[base+1] = x1*s + x2*c;
}

// ---------------- kernel 4: scores = Q K^T * scale (+ causal mask) -------------
__global__ __launch_bounds__(128) void k_scores(const int* __restrict__ causal)
{
    __shared__ __align__(16) float As[64][33];
    __shared__ __align__(16) float Bs[64][33];
    const int z = blockIdx.z;
    const int bm = blockIdx.y * 64, bn = blockIdx.x * 64;
    const int warp = threadIdx.x >> 5, lane = threadIdx.x & 31;
    const int wm = (warp & 1) * 32, wn = (warp >> 1) * 32;
    const float* A  = g_q + (size_t)z*Tn*HDn;
    const float* Bm = g_k + (size_t)z*KVn*HDn;
    float acc[2][4][4] = {};
    for (int kt = 0; kt < HDn; kt += 32) {
        load_tile_rowk(As, A  + (size_t)bm*HDn, HDn, kt);
        load_tile_rowk(Bs, Bm + (size_t)bn*HDn, HDn, kt);
        __syncthreads();
        compute_kt(acc, As, Bs, wm, wn, lane);
        __syncthreads();
    }
    const int gid = lane >> 2, tig = lane & 3;
    const float scale = 0.08838834764831845f;
    const int cz = *causal;
    float* C = g_s + (size_t)z*Tn*KVn;
#pragma unroll
    for (int mi = 0; mi < 2; mi++) {
#pragma unroll
        for (int rr = 0; rr < 2; rr++) {
            const int m = bm + wm + mi*16 + gid + rr*8;
#pragma unroll
            for (int ni = 0; ni < 4; ni++) {
                const int n = bn + wn + ni*8 + tig*2;
                float v0 = acc[mi][ni][rr*2]   * scale;
                float v1 = acc[mi][ni][rr*2+1] * scale;
                if (cz) {
                    if (n   > m + (KVn - Tn)) v0 = -3.402823466e38f;
                    if (n+1 > m + (KVn - Tn)) v1 = -3.402823466e38f;
                }
                *(float2*)&C[(size_t)m*KVn + n] = make_float2(v0, v1);
            }
        }
    }
}

// ---------------- kernel 5: row softmax over 2048 ------------------------------
__global__ __launch_bounds__(256) void k_softmax()
{
    const size_t row = blockIdx.x;
    float* p = g_s + row * (size_t)KVn;
    const int tid = threadIdx.x;
    float4 a = *(float4*)(p + tid*4);
    float4 b = *(float4*)(p + 1024 + tid*4);
    __shared__ float red[8];

    float m = fmaxf(fmaxf(fmaxf(a.x,a.y),fmaxf(a.z,a.w)),
                    fmaxf(fmaxf(b.x,b.y),fmaxf(b.z,b.w)));
#pragma unroll
    for (int o=16;o>0;o>>=1) m = fmaxf(m, __shfl_xor_sync(0xffffffffu, m, o));
    if ((tid & 31) == 0) red[tid>>5] = m;
    __syncthreads();
    float M = red[0];
#pragma unroll
    for (int w=1;w<8;w++) M = fmaxf(M, red[w]);
    __syncthreads();

    a.x = __expf(a.x - M); a.y = __expf(a.y - M);
    a.z = __expf(a.z - M); a.w = __expf(a.w - M);
    b.x = __expf(b.x - M); b.y = __expf(b.y - M);
    b.z = __expf(b.z - M); b.w = __expf(b.w - M);
    float s = a.x+a.y+a.z+a.w+b.x+b.y+b.z+b.w;
#pragma unroll
    for (int o=16;o>0;o>>=1) s += __shfl_xor_sync(0xffffffffu, s, o);
    if ((tid & 31) == 0) red[tid>>5] = s;
    __syncthreads();
    float S = 0.f;
#pragma unroll
    for (int w=0;w<8;w++) S += red[w];
    const float inv = 1.0f / S;

    a.x*=inv; a.y*=inv; a.z*=inv; a.w*=inv;
    b.x*=inv; b.y*=inv; b.z*=inv; b.w*=inv;
    *(float4*)(p + tid*4) = a;
    *(float4*)(p + 1024 + tid*4) = b;
}

// ---------------- kernel 6: y = P V  (NN), store to (B,T,C) --------------------
__global__ __launch_bounds__(128) void k_pv()
{
    __shared__ __align__(16) float As[64][33];
    __shared__ __align__(16) float Bs[64][33];
    const int z = blockIdx.z;
    const int hb = z >> 4, hh = z & 15;
    const int bm = blockIdx.y * 64, bn = blockIdx.x * 64;
    const int warp = threadIdx.x >> 5, lane = threadIdx.x & 31;
    const int wm = (warp & 1) * 32, wn = (warp >> 1) * 32;
    const float* A  = g_s + (size_t)z*Tn*KVn;
    const float* Bm = g_v + (size_t)z*KVn*HDn;
    float acc[2][4][4] = {};
    for (int kt = 0; kt < KVn; kt += 32) {
        load_tile_rowk(As, A + (size_t)bm*KVn, KVn, kt);
        load_tile_kn  (Bs, Bm + bn,            HDn, kt);
        __syncthreads();
        compute_kt(acc, As, Bs, wm, wn, lane);
        __syncthreads();
    }
    const int gid = lane >> 2, tig = lane & 3;
#pragma unroll
    for (int mi = 0; mi < 2; mi++) {
#pragma unroll
        for (int rr = 0; rr < 2; rr++) {
            const int m = bm + wm + mi*16 + gid + rr*8;   // query t
#pragma unroll
            for (int ni = 0; ni < 4; ni++) {
                const int n = bn + wn + ni*8 + tig*2;     // head dim d
                *(float2*)&g_y[((size_t)(hb*Tn + m))*Dn + hh*HDn + n] =
                    make_float2(acc[mi][ni][rr*2], acc[mi][ni][rr*2+1]);
            }
        }
    }
}

// ---------------- kernel 7: out = y @ w_proj^T ---------------------------------
__global__ __launch_bounds__(128) void k_proj(
    const float* __restrict__ w_proj, float* __restrict__ out)
{
    __shared__ __align__(16) float As[64][33];
    __shared__ __align__(16) float Bs[64][33];
    const int bm = blockIdx.y * 64, bn = blockIdx.x * 64;
    const int warp = threadIdx.x >> 5, lane = threadIdx.x & 31;
    const int wm = (warp & 1) * 32, wn = (warp >> 1) * 32;
    float acc[2][4][4] = {};
    for (int kt = 0; kt < Dn; kt += 32) {
        load_tile_rowk(As, g_y    + (size_t)bm*Dn, Dn, kt);
        load_tile_rowk(Bs, w_proj + (size_t)bn*Dn, Dn, kt);
        __syncthreads();
        compute_kt(acc, As, Bs, wm, wn, lane);
        __syncthreads();
    }
    const int gid = lane >> 2, tig = lane & 3;
#pragma unroll
    for (int mi = 0; mi < 2; mi++) {
#pragma unroll
        for (int rr = 0; rr < 2; rr++) {
            const int m = bm + wm + mi*16 + gid + rr*8;
#pragma unroll
            for (int ni = 0; ni < 4; ni++) {
                const int n = bn + wn + ni*8 + tig*2;
                *(float2*)&out[(size_t)m*Dn + n] =
                    make_float2(acc[mi][ni][rr*2], acc[mi][ni][rr*2+1]);
            }
        }
    }
}

// ---------------- launch ------------------------------------------------------
extern "C" void kernel_launch(void* const* d_in, const int* in_sizes, int n_in,
                              void* d_out, int out_size)
{
    const float* x       = (const float*)d_in[0];
    const float* cosb    = (const float*)d_in[1];
    const float* sinb    = (const float*)d_in[2];
    const float* k_xl    = (const float*)d_in[3];
    const float* v_xl    = (const float*)d_in[4];
    const float* pos_emb = (const float*)d_in[5];
    const float* w_qkv   = (const float*)d_in[6];
    const float* w_proj  = (const float*)d_in[7];
    const int*   causal  = (const int*)d_in[8];
    float* out = (float*)d_out;

    k_qkv_gemm<<<dim3(3*Dn/64, Bn*Tn/64), 128>>>(x, w_qkv);
    k_xl_prep<<<(Bn*XLn*Dn)/256, 256>>>(k_xl, v_xl, pos_emb);
    k_rope<<<(2*Bn*Hn*Tn*(HDn/2))/256, 256>>>(cosb, sinb);
    k_scores<<<dim3(KVn/64, Tn/64, Bn*Hn), 128>>>(causal);
    k_softmax<<<Bn*Hn*Tn, 256>>>();
    k_pv<<<dim3(HDn/64, Tn/64, Bn*Hn), 128>>>();
    k_proj<<<dim3(Dn/64, Bn*Tn/64), 128>>>(w_proj, out);
}

// round 5
// speedup vs baseline: 3.4184x; 2.0896x over previous
#include <cuda_runtime.h>
#include <math.h>

#define Bn  2
#define Tn  1024
#define Hn  16
#define HDn 128
#define Dn  2048
#define XLn 1024
#define KVn 2048

// ---------------- scratch -----------------------------------------------------
__device__ float g_q[Bn*Hn*Tn*HDn];            // (B,H,T,hd)   tf32-rounded
__device__ float g_k[Bn*Hn*KVn*HDn];           // (B,H,KV,hd)  tf32-rounded
__device__ float g_v[Bn*Hn*KVn*HDn];           // (B,H,KV,hd)  tf32-rounded
__device__ float g_s[(size_t)Bn*Hn*Tn*KVn];    // (B*H,T,KV)
__device__ float g_y[Bn*Tn*Dn];                // (B,T,C)      tf32-rounded
__device__ float g_x[Bn*Tn*Dn];                // rounded x
__device__ float g_wq[3*Dn*Dn];                // rounded w_qkv
__device__ float g_wp[Dn*Dn];                  // rounded w_proj

// ---------------- helpers -----------------------------------------------------
__device__ __forceinline__ float f2tf(float x) {
    unsigned r; asm("cvt.rna.tf32.f32 %0, %1;" : "=r"(r) : "f"(x));
    return __uint_as_float(r);
}

__device__ __forceinline__ void mma8(float* d,
    unsigned a0, unsigned a1, unsigned a2, unsigned a3,
    unsigned b0, unsigned b1)
{
    asm volatile(
        "mma.sync.aligned.m16n8k8.row.col.f32.tf32.tf32.f32 "
        "{%0,%1,%2,%3}, {%4,%5,%6,%7}, {%8,%9}, {%0,%1,%2,%3};"
        : "+f"(d[0]), "+f"(d[1]), "+f"(d[2]), "+f"(d[3])
        : "r"(a0), "r"(a1), "r"(a2), "r"(a3), "r"(b0), "r"(b1));
}

__device__ __forceinline__ void ldsm4(unsigned &r0, unsigned &r1,
                                      unsigned &r2, unsigned &r3,
                                      const float* p)
{
    unsigned addr = (unsigned)__cvta_generic_to_shared(p);
    asm volatile("ldmatrix.sync.aligned.m8n8.x4.shared.b16 {%0,%1,%2,%3}, [%4];"
                 : "=r"(r0), "=r"(r1), "=r"(r2), "=r"(r3) : "r"(addr));
}

// swizzled index into a [128 rows][16 floats] tile (conflict-free STS.128 + LDSM)
__device__ __forceinline__ int swz16(int r, int c) {
    return r*16 + (c ^ (((r >> 1) & 3) << 2));
}

// ---- tile fills (NT: row-major, K contiguous) --------------------------------
__device__ __forceinline__ void nt_fill(const float* __restrict__ A, size_t lda,
                                        int kt, int tid, float4* pa)
{
#pragma unroll
    for (int p = 0; p < 2; p++) {
        int idx = p*256 + tid;
        int r = idx >> 2, c = (idx & 3) << 2;
        pa[p] = *(const float4*)(A + (size_t)r*lda + kt + c);
    }
}
__device__ __forceinline__ void nt_sts(float* S, int tid, const float4* pa)
{
#pragma unroll
    for (int p = 0; p < 2; p++) {
        int idx = p*256 + tid;
        int r = idx >> 2, c = (idx & 3) << 2;
        *(float4*)&S[swz16(r, c)] = pa[p];
    }
}
// ---- NN B fill (K x N row-major -> S[n][k]) ----------------------------------
__device__ __forceinline__ void nn_fill(const float* __restrict__ B, size_t ldb,
                                        int kt, int tid, float4* pb)
{
#pragma unroll
    for (int p = 0; p < 2; p++) {
        int idx = p*256 + tid;
        int kr = idx >> 5, nc = (idx & 31) << 2;
        pb[p] = *(const float4*)(B + (size_t)(kt + kr)*ldb + nc);
    }
}
__device__ __forceinline__ void nn_sts(float* S, int tid, const float4* pb)
{
#pragma unroll
    for (int p = 0; p < 2; p++) {
        int idx = p*256 + tid;
        int kr = idx >> 5, nc = (idx & 31) << 2;
        S[swz16(nc+0, kr)] = pb[p].x;
        S[swz16(nc+1, kr)] = pb[p].y;
        S[swz16(nc+2, kr)] = pb[p].z;
        S[swz16(nc+3, kr)] = pb[p].w;
    }
}

// ---- one 16-deep K stage of warp mma -----------------------------------------
__device__ __forceinline__ void mma_stage(const float* SA, const float* SB,
    int wm, int wn, int lane, float (&acc)[4][4][4])
{
    const int a_r = lane & 15;
    const int a_c = (lane >> 4) << 2;
    const int b_r = (lane & 7) | ((lane >> 4) << 3);
    const int b_c = ((lane >> 3) & 1) << 2;
#pragma unroll
    for (int k8 = 0; k8 < 2; k8++) {
        const int k0 = k8*8;
        unsigned a[4][4], b[4][2];
#pragma unroll
        for (int mi = 0; mi < 4; mi++) {
            int r = wm + mi*16 + a_r;
            ldsm4(a[mi][0], a[mi][1], a[mi][2], a[mi][3],
                  &SA[swz16(r, k0 + a_c)]);
        }
#pragma unroll
        for (int np = 0; np < 2; np++) {
            int r = wn + np*16 + b_r;
            ldsm4(b[2*np][0], b[2*np][1], b[2*np+1][0], b[2*np+1][1],
                  &SB[swz16(r, k0 + b_c)]);
        }
#pragma unroll
        for (int mi = 0; mi < 4; mi++)
#pragma unroll
            for (int ni = 0; ni < 4; ni++)
                mma8(acc[mi][ni], a[mi][0], a[mi][1], a[mi][2], a[mi][3],
                     b[ni][0], b[ni][1]);
    }
}

// ---- drivers -----------------------------------------------------------------
__device__ __forceinline__ void run_nt(const float* A, size_t lda,
                                       const float* B, size_t ldb, int K,
                                       float (&acc)[4][4][4],
                                       float (*SA)[2048], float (*SB)[2048])
{
    const int tid = threadIdx.x, lane = tid & 31, warp = tid >> 5;
    const int wm = (warp & 1)*64, wn = (warp >> 1)*32;
    float4 pa[2], pb[2];
    nt_fill(A, lda, 0, tid, pa);
    nt_fill(B, ldb, 0, tid, pb);
    nt_sts(SA[0], tid, pa);
    nt_sts(SB[0], tid, pb);
    int cur = 0;
    for (int kt = 0; kt < K; kt += 16) {
        __syncthreads();
        const bool has = (kt + 16) < K;
        if (has) { nt_fill(A, lda, kt+16, tid, pa); nt_fill(B, ldb, kt+16, tid, pb); }
        mma_stage(SA[cur], SB[cur], wm, wn, lane, acc);
        if (has) { nt_sts(SA[cur^1], tid, pa); nt_sts(SB[cur^1], tid, pb); }
        cur ^= 1;
    }
}

__device__ __forceinline__ void run_nn(const float* A, size_t lda,
                                       const float* B, size_t ldb, int K,
                                       float (&acc)[4][4][4],
                                       float (*SA)[2048], float (*SB)[2048])
{
    const int tid = threadIdx.x, lane = tid & 31, warp = tid >> 5;
    const int wm = (warp & 1)*64, wn = (warp >> 1)*32;
    float4 pa[2], pb[2];
    nt_fill(A, lda, 0, tid, pa);
    nn_fill(B, ldb, 0, tid, pb);
    nt_sts(SA[0], tid, pa);
    nn_sts(SB[0], tid, pb);
    int cur = 0;
    for (int kt = 0; kt < K; kt += 16) {
        __syncthreads();
        const bool has = (kt + 16) < K;
        if (has) { nt_fill(A, lda, kt+16, tid, pa); nn_fill(B, ldb, kt+16, tid, pb); }
        mma_stage(SA[cur], SB[cur], wm, wn, lane, acc);
        if (has) { nt_sts(SA[cur^1], tid, pa); nn_sts(SB[cur^1], tid, pb); }
        cur ^= 1;
    }
}

// ---------------- kernel 0: tf32 pre-round ------------------------------------
__global__ __launch_bounds__(256) void k_round4(
    const float4* __restrict__ src, float4* __restrict__ dst, int n4)
{
    int i = blockIdx.x*256 + threadIdx.x;
    if (i < n4) {
        float4 v = src[i];
        v.x = f2tf(v.x); v.y = f2tf(v.y); v.z = f2tf(v.z); v.w = f2tf(v.w);
        dst[i] = v;
    }
}

// ---------------- kernel 1: qkv = x @ w_qkv^T, scatter into q/k/v --------------
__global__ __launch_bounds__(256) void k_qkv_gemm()
{
    __shared__ __align__(16) float SA[2][2048];
    __shared__ __align__(16) float SB[2][2048];
    const int bm = blockIdx.y*128, bn = blockIdx.x*128;
    float acc[4][4][4] = {};
    run_nt(g_x + (size_t)bm*Dn, Dn, g_wq + (size_t)bn*Dn, Dn, Dn, acc, SA, SB);
    const int lane = threadIdx.x & 31, warp = threadIdx.x >> 5;
    const int wm = (warp & 1)*64, wn = (warp >> 1)*32;
    const int gid = lane >> 2, tig = lane & 3;
#pragma unroll
    for (int mi = 0; mi < 4; mi++)
#pragma unroll
    for (int rr = 0; rr < 2; rr++) {
        const int m = bm + wm + mi*16 + rr*8 + gid;
        const int b = m >> 10, t = m & 1023;
#pragma unroll
        for (int ni = 0; ni < 4; ni++) {
            const int n = bn + wn + ni*8 + tig*2;
            const int sec = n >> 11, c = n & 2047;
            const int h = c >> 7, d = c & 127;
            float2 v = make_float2(f2tf(acc[mi][ni][rr*2]), f2tf(acc[mi][ni][rr*2+1]));
            if (sec == 0)
                *(float2*)&g_q[((size_t)(b*Hn+h)*Tn  + t      )*HDn + d] = v;
            else if (sec == 1)
                *(float2*)&g_k[((size_t)(b*Hn+h)*KVn + XLn + t)*HDn + d] = v;
            else
                *(float2*)&g_v[((size_t)(b*Hn+h)*KVn + XLn + t)*HDn + d] = v;
        }
    }
}

// ---------------- kernel 2: k_xl + pos_emb, v_xl → head layout -----------------
__global__ __launch_bounds__(256) void k_xl_prep(
    const float* __restrict__ k_xl, const float* __restrict__ v_xl,
    const float* __restrict__ pos_emb)
{
    const int idx = blockIdx.x*256 + threadIdx.x;
    if (idx >= Bn*XLn*Dn) return;
    const int c = idx & 2047;
    const int pos = (idx >> 11) & 1023;
    const int b = idx >> 21;
    const int h = c >> 7, d = c & 127;
    const size_t dst = ((size_t)(b*Hn+h)*KVn + pos)*HDn + d;
    g_k[dst] = f2tf(k_xl[idx] + pos_emb[pos*Dn + c]);
    g_v[dst] = f2tf(v_xl[idx]);
}

// ---------------- kernel 3: RoPE on q and new k --------------------------------
__global__ __launch_bounds__(256) void k_rope(
    const float* __restrict__ cosb, const float* __restrict__ sinb)
{
    const int idx = blockIdx.x*256 + threadIdx.x;
    const int half = Bn*Hn*Tn*(HDn/2);
    if (idx >= 2*half) return;
    const int isK = idx >= half;
    const int p = idx - (isK ? half : 0);
    const int j = p & 63;
    const int t = (p >> 6) & 1023;
    const int h = (p >> 16) & 15;
    const int b = p >> 20;
    float* buf = isK ? g_k : g_q;
    const size_t base = isK
        ? ((size_t)(b*Hn+h)*KVn + XLn + t)*HDn + 2*j
        : ((size_t)(b*Hn+h)*Tn  + t      )*HDn + 2*j;
    const float c = cosb[t*64 + j];
    const float s = sinb[t*64 + j];
    const float x1 = buf[base], x2 = buf[base+1];
    buf[base]   = f2tf(x1*c - x2*s);
    buf[base+1] = f2tf(x1*s + x2*c);
}

// ---------------- kernel 4: scores = Q K^T * scale (+ causal mask) -------------
__global__ __launch_bounds__(256) void k_scores(const int* __restrict__ causal)
{
    __shared__ __align__(16) float SA[2][2048];
    __shared__ __align__(16) float SB[2][2048];
    const int z = blockIdx.z;
    const int bm = blockIdx.y*128, bn = blockIdx.x*128;
    float acc[4][4][4] = {};
    run_nt(g_q + (size_t)z*Tn*HDn  + (size_t)bm*HDn, HDn,
           g_k + (size_t)z*KVn*HDn + (size_t)bn*HDn, HDn, HDn, acc, SA, SB);
    const int lane = threadIdx.x & 31, warp = threadIdx.x >> 5;
    const int wm = (warp & 1)*64, wn = (warp >> 1)*32;
    const int gid = lane >> 2, tig = lane & 3;
    const float scale = 0.08838834764831845f;
    const int cz = *causal;
    float* C = g_s + (size_t)z*Tn*KVn;
#pragma unroll
    for (int mi = 0; mi < 4; mi++)
#pragma unroll
    for (int rr = 0; rr < 2; rr++) {
        const int m = bm + wm + mi*16 + rr*8 + gid;
#pragma unroll
        for (int ni = 0; ni < 4; ni++) {
            const int n = bn + wn + ni*8 + tig*2;
            float v0 = acc[mi][ni][rr*2]   * scale;
            float v1 = acc[mi][ni][rr*2+1] * scale;
            if (cz) {
                if (n   > m + (KVn - Tn)) v0 = -3.402823466e38f;
                if (n+1 > m + (KVn - Tn)) v1 = -3.402823466e38f;
            }
            *(float2*)&C[(size_t)m*KVn + n] = make_float2(v0, v1);
        }
    }
}

// ---------------- kernel 5: row softmax over 2048 (tf32-rounded out) -----------
__global__ __launch_bounds__(256) void k_softmax()
{
    const size_t row = blockIdx.x;
    float* p = g_s + row * (size_t)KVn;
    const int tid = threadIdx.x;
    float4 a = *(float4*)(p + tid*4);
    float4 b = *(float4*)(p + 1024 + tid*4);
    __shared__ float red[8];

    float m = fmaxf(fmaxf(fmaxf(a.x,a.y),fmaxf(a.z,a.w)),
                    fmaxf(fmaxf(b.x,b.y),fmaxf(b.z,b.w)));
#pragma unroll
    for (int o=16;o>0;o>>=1) m = fmaxf(m, __shfl_xor_sync(0xffffffffu, m, o));
    if ((tid & 31) == 0) red[tid>>5] = m;
    __syncthreads();
    float M = red[0];
#pragma unroll
    for (int w=1;w<8;w++) M = fmaxf(M, red[w]);
    __syncthreads();

    a.x = __expf(a.x - M); a.y = __expf(a.y - M);
    a.z = __expf(a.z - M); a.w = __expf(a.w - M);
    b.x = __expf(b.x - M); b.y = __expf(b.y - M);
    b.z = __expf(b.z - M); b.w = __expf(b.w - M);
    float s = a.x+a.y+a.z+a.w+b.x+b.y+b.z+b.w;
#pragma unroll
    for (int o=16;o>0;o>>=1) s += __shfl_xor_sync(0xffffffffu, s, o);
    if ((tid & 31) == 0) red[tid>>5] = s;
    __syncthreads();
    float S = 0.f;
#pragma unroll
    for (int w=0;w<8;w++) S += red[w];
    const float inv = 1.0f / S;

    a.x = f2tf(a.x*inv); a.y = f2tf(a.y*inv);
    a.z = f2tf(a.z*inv); a.w = f2tf(a.w*inv);
    b.x = f2tf(b.x*inv); b.y = f2tf(b.y*inv);
    b.z = f2tf(b.z*inv); b.w = f2tf(b.w*inv);
    *(float4*)(p + tid*4) = a;
    *(float4*)(p + 1024 + tid*4) = b;
}

// ---------------- kernel 6: y = P V  (NN), store to (B,T,C) --------------------
__global__ __launch_bounds__(256) void k_pv()
{
    __shared__ __align__(16) float SA[2][2048];
    __shared__ __align__(16) float SB[2][2048];
    const int z = blockIdx.z;
    const int hb = z >> 4, hh = z & 15;
    const int bm = blockIdx.y*128;  // bn = 0 (N = 128)
    float acc[4][4][4] = {};
    run_nn(g_s + (size_t)z*Tn*KVn + (size_t)bm*KVn, KVn,
           g_v + (size_t)z*KVn*HDn, HDn, KVn, acc, SA, SB);
    const int lane = threadIdx.x & 31, warp = threadIdx.x >> 5;
    const int wm = (warp & 1)*64, wn = (warp >> 1)*32;
    const int gid = lane >> 2, tig = lane & 3;
#pragma unroll
    for (int mi = 0; mi < 4; mi++)
#pragma unroll
    for (int rr = 0; rr < 2; rr++) {
        const int m = bm + wm + mi*16 + rr*8 + gid;   // query t
#pragma unroll
        for (int ni = 0; ni < 4; ni++) {
            const int n = wn + ni*8 + tig*2;          // head dim d
            *(float2*)&g_y[((size_t)(hb*Tn + m))*Dn + hh*HDn + n] =
                make_float2(f2tf(acc[mi][ni][rr*2]), f2tf(acc[mi][ni][rr*2+1]));
        }
    }
}

// ---------------- kernel 7: out = y @ w_proj^T ---------------------------------
__global__ __launch_bounds__(256) void k_proj(float* __restrict__ out)
{
    __shared__ __align__(16) float SA[2][2048];
    __shared__ __align__(16) float SB[2][2048];
    const int bm = blockIdx.y*128, bn = blockIdx.x*128;
    float acc[4][4][4] = {};
    run_nt(g_y + (size_t)bm*Dn, Dn, g_wp + (size_t)bn*Dn, Dn, Dn, acc, SA, SB);
    const int lane = threadIdx.x & 31, warp = threadIdx.x >> 5;
    const int wm = (warp & 1)*64, wn = (warp >> 1)*32;
    const int gid = lane >> 2, tig = lane & 3;
#pragma unroll
    for (int mi = 0; mi < 4; mi++)
#pragma unroll
    for (int rr = 0; rr < 2; rr++) {
        const int m = bm + wm + mi*16 + rr*8 + gid;
#pragma unroll
        for (int ni = 0; ni < 4; ni++) {
            const int n = bn + wn + ni*8 + tig*2;
            *(float2*)&out[(size_t)m*Dn + n] =
                make_float2(acc[mi][ni][rr*2], acc[mi][ni][rr*2+1]);
        }
    }
}

// ---------------- launch ------------------------------------------------------
extern "C" void kernel_launch(void* const* d_in, const int* in_sizes, int n_in,
                              void* d_out, int out_size)
{
    const float* x       = (const float*)d_in[0];
    const float* cosb    = (const float*)d_in[1];
    const float* sinb    = (const float*)d_in[2];
    const float* k_xl    = (const float*)d_in[3];
    const float* v_xl    = (const float*)d_in[4];
    const float* pos_emb = (const float*)d_in[5];
    const float* w_qkv   = (const float*)d_in[6];
    const float* w_proj  = (const float*)d_in[7];
    const int*   causal  = (const int*)d_in[8];
    float* out = (float*)d_out;

    float *gx, *gwq, *gwp;
    cudaGetSymbolAddress((void**)&gx,  g_x);
    cudaGetSymbolAddress((void**)&gwq, g_wq);
    cudaGetSymbolAddress((void**)&gwp, g_wp);

    // 0) tf32 pre-round of GEMM inputs
    k_round4<<<(Bn*Tn*Dn/4 + 255)/256, 256>>>((const float4*)x,      (float4*)gx,  Bn*Tn*Dn/4);
    k_round4<<<(3*Dn*Dn/4  + 255)/256, 256>>>((const float4*)w_qkv,  (float4*)gwq, 3*Dn*Dn/4);
    k_round4<<<(Dn*Dn/4    + 255)/256, 256>>>((const float4*)w_proj, (float4*)gwp, Dn*Dn/4);

    // 1) qkv GEMM
    k_qkv_gemm<<<dim3(3*Dn/128, Bn*Tn/128), 256>>>();

    // 2) XL cache prep
    k_xl_prep<<<(Bn*XLn*Dn)/256, 256>>>(k_xl, v_xl, pos_emb);

    // 3) RoPE
    k_rope<<<(2*Bn*Hn*Tn*(HDn/2))/256, 256>>>(cosb, sinb);

    // 4) scores
    k_scores<<<dim3(KVn/128, Tn/128, Bn*Hn), 256>>>(causal);

    // 5) softmax
    k_softmax<<<Bn*Hn*Tn, 256>>>();

    // 6) P @ V
    k_pv<<<dim3(1, Tn/128, Bn*Hn), 256>>>();

    // 7) output projection
    k_proj<<<dim3(Dn/128, Bn*Tn/128), 256>>>(out);
}

// round 10
// speedup vs baseline: 4.1374x; 1.2103x over previous
#include <cuda_runtime.h>
#include <cstdint>
#include <math.h>

#define Bn  2
#define Tn  1024
#define Hn  16
#define HDn 128
#define Dn  2048
#define XLn 1024
#define KVn 2048

// ---------------- scratch -----------------------------------------------------
__device__ float g_q [Bn*Hn*Tn*HDn];            // (B,H,T,hd)   tf32-rounded
__device__ float g_k [Bn*Hn*KVn*HDn];           // (B,H,KV,hd)  tf32-rounded
__device__ float g_v [Bn*Hn*KVn*HDn];           // (B,H,KV,hd)  tf32-rounded
__device__ float g_vt[Bn*Hn*HDn*KVn];           // (B,H,hd,KV)  transposed V
__device__ float g_y [Bn*Tn*Dn];                // (B,T,C)      tf32-rounded
__device__ float g_x [Bn*Tn*Dn];                // rounded x
__device__ float g_wq[3*Dn*Dn];                 // rounded w_qkv
__device__ float g_wp[Dn*Dn];                   // rounded w_proj

// ---------------- helpers -----------------------------------------------------
__device__ __forceinline__ float f2tf(float x) {
    unsigned r; asm("cvt.rna.tf32.f32 %0, %1;" : "=r"(r) : "f"(x));
    return __uint_as_float(r);
}

__device__ __forceinline__ void mma8(float* d,
    unsigned a0, unsigned a1, unsigned a2, unsigned a3,
    unsigned b0, unsigned b1)
{
    asm volatile(
        "mma.sync.aligned.m16n8k8.row.col.f32.tf32.tf32.f32 "
        "{%0,%1,%2,%3}, {%4,%5,%6,%7}, {%8,%9}, {%0,%1,%2,%3};"
        : "+f"(d[0]), "+f"(d[1]), "+f"(d[2]), "+f"(d[3])
        : "r"(a0), "r"(a1), "r"(a2), "r"(a3), "r"(b0), "r"(b1));
}

__device__ __forceinline__ void ldsm4(unsigned &r0, unsigned &r1,
                                      unsigned &r2, unsigned &r3,
                                      const float* p)
{
    unsigned addr = (unsigned)__cvta_generic_to_shared(p);
    asm volatile("ldmatrix.sync.aligned.m8n8.x4.shared.b16 {%0,%1,%2,%3}, [%4];"
                 : "=r"(r0), "=r"(r1), "=r"(r2), "=r"(r3) : "r"(addr));
}

// swizzled index into [rows][16 floats] tiles (conflict-free STS.128 + LDSM)
__device__ __forceinline__ int swz16(int r, int c) {
    return r*16 + (c ^ (((r >> 1) & 3) << 2));
}

__device__ __forceinline__ void cpa16(uint32_t dst, const void* src) {
    asm volatile("cp.async.cg.shared.global [%0], [%1], 16;" :: "r"(dst), "l"(src));
}
__device__ __forceinline__ uint32_t smem_u32(const void* p) {
    return (uint32_t)__cvta_generic_to_shared(p);
}
#define CP_COMMIT() asm volatile("cp.async.commit_group;" ::: "memory")

// ---- GEMM tile fills (NT: row-major, K contiguous) ---------------------------
__device__ __forceinline__ void nt_fill(const float* __restrict__ A, size_t lda,
                                        int kt, int tid, float4* pa)
{
#pragma unroll
    for (int p = 0; p < 2; p++) {
        int idx = p*256 + tid;
        int r = idx >> 2, c = (idx & 3) << 2;
        pa[p] = *(const float4*)(A + (size_t)r*lda + kt + c);
    }
}
__device__ __forceinline__ void nt_sts(float* S, int tid, const float4* pa)
{
#pragma unroll
    for (int p = 0; p < 2; p++) {
        int idx = p*256 + tid;
        int r = idx >> 2, c = (idx & 3) << 2;
        *(float4*)&S[swz16(r, c)] = pa[p];
    }
}

// ---- one 16-deep K stage of warp mma (proven round-5 mapping) ----------------
__device__ __forceinline__ void mma_stage(const float* SA, const float* SB,
    int wm, int wn, int lane, float (&acc)[4][4][4])
{
    const int a_r = lane & 15;
    const int a_c = (lane >> 4) << 2;
    const int b_r = (lane & 7) | ((lane >> 4) << 3);
    const int b_c = ((lane >> 3) & 1) << 2;
#pragma unroll
    for (int k8 = 0; k8 < 2; k8++) {
        const int k0 = k8*8;
        unsigned a[4][4], b[4][2];
#pragma unroll
        for (int mi = 0; mi < 4; mi++) {
            int r = wm + mi*16 + a_r;
            ldsm4(a[mi][0], a[mi][1], a[mi][2], a[mi][3],
                  &SA[swz16(r, k0 + a_c)]);
        }
#pragma unroll
        for (int np = 0; np < 2; np++) {
            int r = wn + np*16 + b_r;
            ldsm4(b[2*np][0], b[2*np][1], b[2*np+1][0], b[2*np+1][1],
                  &SB[swz16(r, k0 + b_c)]);
        }
#pragma unroll
        for (int mi = 0; mi < 4; mi++)
#pragma unroll
            for (int ni = 0; ni < 4; ni++)
                mma8(acc[mi][ni], a[mi][0], a[mi][1], a[mi][2], a[mi][3],
                     b[ni][0], b[ni][1]);
    }
}

__device__ __forceinline__ void run_nt(const float* A, size_t lda,
                                       const float* B, size_t ldb, int K,
                                       float (&acc)[4][4][4],
                                       float (*SA)[2048], float (*SB)[2048])
{
    const int tid = threadIdx.x, lane = tid & 31, warp = tid >> 5;
    const int wm = (warp & 1)*64, wn = (warp >> 1)*32;
    float4 pa[2], pb[2];
    nt_fill(A, lda, 0, tid, pa);
    nt_fill(B, ldb, 0, tid, pb);
    nt_sts(SA[0], tid, pa);
    nt_sts(SB[0], tid, pb);
    int cur = 0;
    for (int kt = 0; kt < K; kt += 16) {
        __syncthreads();
        const bool has = (kt + 16) < K;
        if (has) { nt_fill(A, lda, kt+16, tid, pa); nt_fill(B, ldb, kt+16, tid, pb); }
        mma_stage(SA[cur], SB[cur], wm, wn, lane, acc);
        if (has) { nt_sts(SA[cur^1], tid, pa); nt_sts(SB[cur^1], tid, pb); }
        cur ^= 1;
    }
}

// ---------------- kernel 0: tf32 pre-round ------------------------------------
__global__ __launch_bounds__(256) void k_round4(
    const float4* __restrict__ src, float4* __restrict__ dst, int n4)
{
    int i = blockIdx.x*256 + threadIdx.x;
    if (i < n4) {
        float4 v = src[i];
        v.x = f2tf(v.x); v.y = f2tf(v.y); v.z = f2tf(v.z); v.w = f2tf(v.w);
        dst[i] = v;
    }
}

// ---------------- kernel 1: qkv = x @ w_qkv^T, scatter into q/k/v --------------
__global__ __launch_bounds__(256) void k_qkv_gemm()
{
    __shared__ __align__(16) float SA[2][2048];
    __shared__ __align__(16) float SB[2][2048];
    const int bm = blockIdx.y*128, bn = blockIdx.x*128;
    float acc[4][4][4] = {};
    run_nt(g_x + (size_t)bm*Dn, Dn, g_wq + (size_t)bn*Dn, Dn, Dn, acc, SA, SB);
    const int lane = threadIdx.x & 31, warp = threadIdx.x >> 5;
    const int wm = (warp & 1)*64, wn = (warp >> 1)*32;
    const int gid = lane >> 2, tig = lane & 3;
#pragma unroll
    for (int mi = 0; mi < 4; mi++)
#pragma unroll
    for (int rr = 0; rr < 2; rr++) {
        const int m = bm + wm + mi*16 + rr*8 + gid;
        const int b = m >> 10, t = m & 1023;
#pragma unroll
        for (int ni = 0; ni < 4; ni++) {
            const int n = bn + wn + ni*8 + tig*2;
            const int sec = n >> 11, c = n & 2047;
            const int h = c >> 7, d = c & 127;
            float2 v = make_float2(f2tf(acc[mi][ni][rr*2]), f2tf(acc[mi][ni][rr*2+1]));
            if (sec == 0)
                *(float2*)&g_q[((size_t)(b*Hn+h)*Tn  + t      )*HDn + d] = v;
            else if (sec == 1)
                *(float2*)&g_k[((size_t)(b*Hn+h)*KVn + XLn + t)*HDn + d] = v;
            else
                *(float2*)&g_v[((size_t)(b*Hn+h)*KVn + XLn + t)*HDn + d] = v;
        }
    }
}

// ---------------- kernel 2: k_xl + pos_emb, v_xl → head layout -----------------
__global__ __launch_bounds__(256) void k_xl_prep(
    const float* __restrict__ k_xl, const float* __restrict__ v_xl,
    const float* __restrict__ pos_emb)
{
    const int idx = blockIdx.x*256 + threadIdx.x;
    if (idx >= Bn*XLn*Dn) return;
    const int c = idx & 2047;
    const int pos = (idx >> 11) & 1023;
    const int b = idx >> 21;
    const int h = c >> 7, d = c & 127;
    const size_t dst = ((size_t)(b*Hn+h)*KVn + pos)*HDn + d;
    g_k[dst] = f2tf(k_xl[idx] + pos_emb[pos*Dn + c]);
    g_v[dst] = f2tf(v_xl[idx]);
}

// ---------------- kernel 3: RoPE on q and new k --------------------------------
__global__ __launch_bounds__(256) void k_rope(
    const float* __restrict__ cosb, const float* __restrict__ sinb)
{
    const int idx = blockIdx.x*256 + threadIdx.x;
    const int half = Bn*Hn*Tn*(HDn/2);
    if (idx >= 2*half) return;
    const int isK = idx >= half;
    const int p = idx - (isK ? half : 0);
    const int j = p & 63;
    const int t = (p >> 6) & 1023;
    const int h = (p >> 16) & 15;
    const int b = p >> 20;
    float* buf = isK ? g_k : g_q;
    const size_t base = isK
        ? ((size_t)(b*Hn+h)*KVn + XLn + t)*HDn + 2*j
        : ((size_t)(b*Hn+h)*Tn  + t      )*HDn + 2*j;
    const float c = cosb[t*64 + j];
    const float s = sinb[t*64 + j];
    const float x1 = buf[base], x2 = buf[base+1];
    buf[base]   = f2tf(x1*c - x2*s);
    buf[base+1] = f2tf(x1*s + x2*c);
}

// ---------------- kernel 3b: V transpose (B,H,KV,hd) -> (B,H,hd,KV) ------------
__global__ __launch_bounds__(256) void k_vtrans()
{
    __shared__ float tile[32][33];
    const int z = blockIdx.z;
    const int kv0 = blockIdx.x*32, d0 = blockIdx.y*32;
    const float* src = g_v  + (size_t)z*KVn*HDn;
    float*       dst = g_vt + (size_t)z*HDn*KVn;
    const int tx = threadIdx.x & 31, ty = threadIdx.x >> 5;
#pragma unroll
    for (int j = 0; j < 4; j++)
        tile[ty + 8*j][tx] = src[(size_t)(kv0 + ty + 8*j)*HDn + d0 + tx];
    __syncthreads();
#pragma unroll
    for (int j = 0; j < 4; j++)
        dst[(size_t)(d0 + ty + 8*j)*KVn + kv0 + tx] = tile[tx][ty + 8*j];
}

// ---------------- kernel 4: fused flash attention ------------------------------
// Per CTA: 128 Q rows x one (b,h). 8 warps, each owns 16 rows.
// SMEM floats: sQ[8][128][16] | sK[2][8][64][16] | sV[2][4][128][16] | sP[4][128][16]
__global__ __launch_bounds__(256, 1) void k_flash(const int* __restrict__ causal)
{
    extern __shared__ float sm[];
    float* sQ  = sm;                      // 16384
    float* sKb[2] = { sm + 16384, sm + 16384 + 8192 };
    float* sVb[2] = { sm + 32768, sm + 32768 + 8192 };
    float* sP  = sm + 49152;              // 8192

    const int z  = blockIdx.y;            // b*H + h
    const int bm = blockIdx.x * 128;
    const int hb = z >> 4, hh = z & 15;
    const int tid = threadIdx.x, lane = tid & 31, warp = tid >> 5;
    const int wm = warp * 16;
    const int gid = lane >> 2, tig = lane & 3;
    const int cz = *causal;

    const int a_r = lane & 15;
    const int a_c = (lane >> 4) << 2;
    const int b_r = (lane & 7) | ((lane >> 4) << 3);
    const int b_c = ((lane >> 3) & 1) << 2;

    const float* Qg  = g_q  + (size_t)z*Tn*HDn + (size_t)bm*HDn;
    const float* Kg  = g_k  + (size_t)z*KVn*HDn;
    const float* Vtg = g_vt + (size_t)z*HDn*KVn;

    // ---- prologue loads ----
#pragma unroll
    for (int i = 0; i < 16; i++) {            // Q: 128x128
        int idx = i*256 + tid, r = idx >> 5, col = (idx & 31)*4;
        cpa16(smem_u32(sQ + (col >> 4)*2048 + swz16(r, col & 15)),
              Qg + (size_t)r*HDn + col);
    }
    CP_COMMIT();
    {
        float* S = sKb[0];
#pragma unroll
        for (int i = 0; i < 8; i++) {         // K chunk 0: 64x128
            int idx = i*256 + tid, r = idx >> 5, col = (idx & 31)*4;
            cpa16(smem_u32(S + (col >> 4)*1024 + swz16(r, col & 15)),
                  Kg + (size_t)r*HDn + col);
        }
        CP_COMMIT();
        float* V = sVb[0];
#pragma unroll
        for (int i = 0; i < 8; i++) {         // Vt chunk 0: 128 x 64
            int idx = i*256 + tid, d = idx >> 4, col = (idx & 15)*4;
            cpa16(smem_u32(V + (col >> 4)*2048 + swz16(d, col & 15)),
                  Vtg + (size_t)d*KVn + col);
        }
        CP_COMMIT();
    }

    float o[16][4] = {};
    float m0 = -1e30f, m1 = -1e30f, l0 = 0.f, l1 = 0.f;
    const float scale = 0.08838834764831845f;
    const int NC = KVn / 64;

    for (int c = 0; c < NC; c++) {
        asm volatile("cp.async.wait_group 1;" ::: "memory");
        __syncthreads();

        if (c + 1 < NC) {
            const int kvn = (c + 1)*64;
            float* S = sKb[(c + 1) & 1];
#pragma unroll
            for (int i = 0; i < 8; i++) {
                int idx = i*256 + tid, r = idx >> 5, col = (idx & 31)*4;
                cpa16(smem_u32(S + (col >> 4)*1024 + swz16(r, col & 15)),
                      Kg + (size_t)(kvn + r)*HDn + col);
            }
            CP_COMMIT();
            float* V = sVb[(c + 1) & 1];
#pragma unroll
            for (int i = 0; i < 8; i++) {
                int idx = i*256 + tid, d = idx >> 4, col = (idx & 15)*4;
                cpa16(smem_u32(V + (col >> 4)*2048 + swz16(d, col & 15)),
                      Vtg + (size_t)d*KVn + kvn + col);
            }
            CP_COMMIT();
        }

        // ---- S = Q K^T (m16 x n64 per warp, k=128) ----
        float s[8][4] = {};
        {
            const float* Kc = sKb[c & 1];
#pragma unroll
            for (int k8 = 0; k8 < 16; k8++) {
                const int k0 = (k8 & 1)*8;
                const float* QS = sQ + (k8 >> 1)*2048;
                unsigned a0, a1, a2, a3;
                ldsm4(a0, a1, a2, a3, &QS[swz16(wm + a_r, k0 + a_c)]);
                const float* KS = Kc + (k8 >> 1)*1024;
                unsigned b[8][2];
#pragma unroll
                for (int np = 0; np < 4; np++)
                    ldsm4(b[2*np][0], b[2*np][1], b[2*np+1][0], b[2*np+1][1],
                          &KS[swz16(np*16 + b_r, k0 + b_c)]);
#pragma unroll
                for (int ni = 0; ni < 8; ni++)
                    mma8(s[ni], a0, a1, a2, a3, b[ni][0], b[ni][1]);
            }
        }

        // ---- online softmax ----
        const int kv0 = c*64;
#pragma unroll
        for (int ni = 0; ni < 8; ni++) {
            s[ni][0] *= scale; s[ni][1] *= scale;
            s[ni][2] *= scale; s[ni][3] *= scale;
        }
        if (cz) {
            const int lim0 = bm + wm + gid + (KVn - Tn);
            const int lim1 = lim0 + 8;
#pragma unroll
            for (int ni = 0; ni < 8; ni++) {
                const int col = kv0 + ni*8 + tig*2;
                if (col     > lim0) s[ni][0] = -1e30f;
                if (col + 1 > lim0) s[ni][1] = -1e30f;
                if (col     > lim1) s[ni][2] = -1e30f;
                if (col + 1 > lim1) s[ni][3] = -1e30f;
            }
        }
        float mx0 = -1e30f, mx1 = -1e30f;
#pragma unroll
        for (int ni = 0; ni < 8; ni++) {
            mx0 = fmaxf(mx0, fmaxf(s[ni][0], s[ni][1]));
            mx1 = fmaxf(mx1, fmaxf(s[ni][2], s[ni][3]));
        }
        mx0 = fmaxf(mx0, __shfl_xor_sync(0xffffffffu, mx0, 1));
        mx0 = fmaxf(mx0, __shfl_xor_sync(0xffffffffu, mx0, 2));
        mx1 = fmaxf(mx1, __shfl_xor_sync(0xffffffffu, mx1, 1));
        mx1 = fmaxf(mx1, __shfl_xor_sync(0xffffffffu, mx1, 2));
        const float mn0 = fmaxf(m0, mx0), mn1 = fmaxf(m1, mx1);
        const float f0 = __expf(m0 - mn0), f1 = __expf(m1 - mn1);
        m0 = mn0; m1 = mn1;
        float ad0 = 0.f, ad1 = 0.f;
#pragma unroll
        for (int ni = 0; ni < 8; ni++) {
            s[ni][0] = __expf(s[ni][0] - m0);
            s[ni][1] = __expf(s[ni][1] - m0);
            s[ni][2] = __expf(s[ni][2] - m1);
            s[ni][3] = __expf(s[ni][3] - m1);
            ad0 += s[ni][0] + s[ni][1];
            ad1 += s[ni][2] + s[ni][3];
        }
        ad0 += __shfl_xor_sync(0xffffffffu, ad0, 1);
        ad0 += __shfl_xor_sync(0xffffffffu, ad0, 2);
        ad1 += __shfl_xor_sync(0xffffffffu, ad1, 1);
        ad1 += __shfl_xor_sync(0xffffffffu, ad1, 2);
        l0 = l0*f0 + ad0;
        l1 = l1*f1 + ad1;
#pragma unroll
        for (int ni = 0; ni < 16; ni++) {
            o[ni][0] *= f0; o[ni][1] *= f0;
            o[ni][2] *= f1; o[ni][3] *= f1;
        }
        // P -> sP (tf32), per-warp private rows
#pragma unroll
        for (int ni = 0; ni < 8; ni++) {
            const int n = ni*8 + tig*2;
            float* base = sP + (n >> 4)*2048;
            *(float2*)&base[swz16(wm + gid,     n & 15)] =
                make_float2(f2tf(s[ni][0]), f2tf(s[ni][1]));
            *(float2*)&base[swz16(wm + 8 + gid, n & 15)] =
                make_float2(f2tf(s[ni][2]), f2tf(s[ni][3]));
        }
        __syncwarp();

        if (c + 1 < NC) asm volatile("cp.async.wait_group 2;" ::: "memory");
        else            asm volatile("cp.async.wait_group 0;" ::: "memory");
        __syncthreads();

        // ---- O += P V  (m16 x n128 per warp, k=64) ----
        {
            const float* Vc = sVb[c & 1];
#pragma unroll
            for (int k8 = 0; k8 < 8; k8++) {
                const int k0 = (k8 & 1)*8;
                const float* PS = sP + (k8 >> 1)*2048;
                unsigned a0, a1, a2, a3;
                ldsm4(a0, a1, a2, a3, &PS[swz16(wm + a_r, k0 + a_c)]);
                const float* VS = Vc + (k8 >> 1)*2048;
                unsigned b[16][2];
#pragma unroll
                for (int np = 0; np < 8; np++)
                    ldsm4(b[2*np][0], b[2*np][1], b[2*np+1][0], b[2*np+1][1],
                          &VS[swz16(np*16 + b_r, k0 + b_c)]);
#pragma unroll
                for (int ni = 0; ni < 16; ni++)
                    mma8(o[ni], a0, a1, a2, a3, b[ni][0], b[ni][1]);
            }
        }
    }

    // ---- epilogue: normalize and store ----
    const float inv0 = 1.0f / l0, inv1 = 1.0f / l1;
    const int t0 = bm + wm + gid;
    float* y0 = g_y + ((size_t)(hb*Tn + t0))*Dn + hh*HDn;
    float* y1 = y0 + (size_t)8*Dn;
#pragma unroll
    for (int ni = 0; ni < 16; ni++) {
        const int d = ni*8 + tig*2;
        *(float2*)&y0[d] = make_float2(f2tf(o[ni][0]*inv0), f2tf(o[ni][1]*inv0));
        *(float2*)&y1[d] = make_float2(f2tf(o[ni][2]*inv1), f2tf(o[ni][3]*inv1));
    }
}

// ---------------- kernel 5: out = y @ w_proj^T ---------------------------------
__global__ __launch_bounds__(256) void k_proj(float* __restrict__ out)
{
    __shared__ __align__(16) float SA[2][2048];
    __shared__ __align__(16) float SB[2][2048];
    const int bm = blockIdx.y*128, bn = blockIdx.x*128;
    float acc[4][4][4] = {};
    run_nt(g_y + (size_t)bm*Dn, Dn, g_wp + (size_t)bn*Dn, Dn, Dn, acc, SA, SB);
    const int lane = threadIdx.x & 31, warp = threadIdx.x >> 5;
    const int wm = (warp & 1)*64, wn = (warp >> 1)*32;
    const int gid = lane >> 2, tig = lane & 3;
#pragma unroll
    for (int mi = 0; mi < 4; mi++)
#pragma unroll
    for (int rr = 0; rr < 2; rr++) {
        const int m = bm + wm + mi*16 + rr*8 + gid;
#pragma unroll
        for (int ni = 0; ni < 4; ni++) {
            const int n = bn + wn + ni*8 + tig*2;
            *(float2*)&out[(size_t)m*Dn + n] =
                make_float2(acc[mi][ni][rr*2], acc[mi][ni][rr*2+1]);
        }
    }
}

// ---------------- launch ------------------------------------------------------
extern "C" void kernel_launch(void* const* d_in, const int* in_sizes, int n_in,
                              void* d_out, int out_size)
{
    const float* x       = (const float*)d_in[0];
    const float* cosb    = (const float*)d_in[1];
    const float* sinb    = (const float*)d_in[2];
    const float* k_xl    = (const float*)d_in[3];
    const float* v_xl    = (const float*)d_in[4];
    const float* pos_emb = (const float*)d_in[5];
    const float* w_qkv   = (const float*)d_in[6];
    const float* w_proj  = (const float*)d_in[7];
    const int*   causal  = (const int*)d_in[8];
    float* out = (float*)d_out;

    float *gx, *gwq, *gwp;
    cudaGetSymbolAddress((void**)&gx,  g_x);
    cudaGetSymbolAddress((void**)&gwq, g_wq);
    cudaGetSymbolAddress((void**)&gwp, g_wp);

    const int SM_FLASH = 57344 * 4;   // 229376 B
    cudaFuncSetAttribute(k_flash, cudaFuncAttributeMaxDynamicSharedMemorySize, SM_FLASH);

    // 0) tf32 pre-round of GEMM inputs
    k_round4<<<(Bn*Tn*Dn/4 + 255)/256, 256>>>((const float4*)x,      (float4*)gx,  Bn*Tn*Dn/4);
    k_round4<<<(3*Dn*Dn/4  + 255)/256, 256>>>((const float4*)w_qkv,  (float4*)gwq, 3*Dn*Dn/4);
    k_round4<<<(Dn*Dn/4    + 255)/256, 256>>>((const float4*)w_proj, (float4*)gwp, Dn*Dn/4);

    // 1) qkv GEMM
    k_qkv_gemm<<<dim3(3*Dn/128, Bn*Tn/128), 256>>>();

    // 2) XL cache prep
    k_xl_prep<<<(Bn*XLn*Dn)/256, 256>>>(k_xl, v_xl, pos_emb);

    // 3) RoPE
    k_rope<<<(2*Bn*Hn*Tn*(HDn/2))/256, 256>>>(cosb, sinb);

    // 3b) V transpose
    k_vtrans<<<dim3(KVn/32, HDn/32, Bn*Hn), 256>>>();

    // 4) fused flash attention (scores + softmax + PV)
    k_flash<<<dim3(Tn/128, Bn*Hn), 256, SM_FLASH>>>(causal);

    // 5) output projection
    k_proj<<<dim3(Dn/128, Bn*Tn/128), 256>>>(out);
}